// round 8
// baseline (speedup 1.0000x reference)
#include <cuda_runtime.h>
#include <cuda_bf16.h>
#include <math.h>
#include <stdint.h>

// Problem constants
#define BATCH   8192
#define FEAT    1024
#define DDIM    4096
#define NSCALE  5
#define NNODES  7
#define NLEAVES 8
#define HID     64
#define NH      448   // NNODES*HID
#define DH      256   // FEAT/4
#define MTOT    704   // NH + DH
#define LN_EPS  1e-5f

// Scratch
__device__ float g_mid[BATCH * MTOT];                 // GEMM output (pre-activation)
__device__ __nv_bfloat16 g_abf[BATCH * FEAT];         // features in bf16
__device__ __nv_bfloat16 g_wbf[MTOT * FEAT];          // fused weights [tw1; dw1] in bf16

__device__ __forceinline__ float gelu_exact(float x) {
    return 0.5f * x * (1.0f + erff(x * 0.70710678118654752440f));
}

__device__ __forceinline__ void mma_bf16(float c[4],
                                         uint32_t a0, uint32_t a1, uint32_t a2, uint32_t a3,
                                         uint32_t b0, uint32_t b1) {
    asm volatile(
        "mma.sync.aligned.m16n8k16.row.col.f32.bf16.bf16.f32 "
        "{%0,%1,%2,%3}, {%4,%5,%6,%7}, {%8,%9}, {%0,%1,%2,%3};\n"
        : "+f"(c[0]), "+f"(c[1]), "+f"(c[2]), "+f"(c[3])
        : "r"(a0), "r"(a1), "r"(a2), "r"(a3), "r"(b0), "r"(b1));
}

__device__ __forceinline__ void cp_async16(uint32_t smem_addr, const void* gptr) {
    asm volatile("cp.async.cg.shared.global [%0], [%1], 16;"
                 :: "r"(smem_addr), "l"(gptr));
}

// ---------------------------------------------------------------------------
// Kernel 0: convert features + fused weights to bf16
// ---------------------------------------------------------------------------
#define A_VEC4 (BATCH * FEAT / 4)      // 2,097,152
#define W_VEC4 (MTOT * FEAT / 4)       // 180,224

__global__ __launch_bounds__(256)
void convert_kernel(const float* __restrict__ feat,
                    const float* __restrict__ tw1,
                    const float* __restrict__ dw1)
{
    int idx = blockIdx.x * 256 + threadIdx.x;
    if (idx < A_VEC4) {
        float4 v = *reinterpret_cast<const float4*>(feat + (size_t)idx * 4);
        __nv_bfloat162 lo = __floats2bfloat162_rn(v.x, v.y);
        __nv_bfloat162 hi = __floats2bfloat162_rn(v.z, v.w);
        uint2 r = make_uint2(*reinterpret_cast<uint32_t*>(&lo),
                             *reinterpret_cast<uint32_t*>(&hi));
        *reinterpret_cast<uint2*>(&g_abf[(size_t)idx * 4]) = r;
    } else if (idx < A_VEC4 + W_VEC4) {
        int w4 = idx - A_VEC4;
        size_t e = (size_t)w4 * 4;
        int row = (int)(e >> 10);
        const float* src = (row < NH) ? (tw1 + e) : (dw1 + e - (size_t)NH * FEAT);
        float4 v = *reinterpret_cast<const float4*>(src);
        __nv_bfloat162 lo = __floats2bfloat162_rn(v.x, v.y);
        __nv_bfloat162 hi = __floats2bfloat162_rn(v.z, v.w);
        uint2 r = make_uint2(*reinterpret_cast<uint32_t*>(&lo),
                             *reinterpret_cast<uint32_t*>(&hi));
        *reinterpret_cast<uint2*>(&g_wbf[e]) = r;
    }
}

// ---------------------------------------------------------------------------
// Kernel 1: cp.async-pipelined bf16 tensor-core GEMM
//   C[b, m] = sum_f A[b,f] * W(m,f) + bias(m), into g_mid.
// BM=128, BN=64, BK=32, 128 threads, 4 warps (2M x 2N), warp tile 64x32.
// 3-stage cp.async pipeline. Smem rows: 32 bf16 = 16 words, padded to 20
// words (80 B) -> conflict-free scalar LDS fragments AND 16B-aligned rows
// for cp.async.
// ---------------------------------------------------------------------------
#define BM 128
#define BN 64
#define BK 32
#define S32 20
#define NSTAGE 3
#define A_ST_WORDS (BM * S32)   // 2560 words = 10240 B
#define B_ST_WORDS (BN * S32)   // 1280 words =  5120 B
#define NSLAB (FEAT / BK)       // 32

__global__ __launch_bounds__(128)
void gemm_tc_kernel(const float* __restrict__ tb1,
                    const float* __restrict__ db1)
{
    __shared__ __align__(16) uint32_t As[NSTAGE * A_ST_WORDS];  // 30720 B
    __shared__ __align__(16) uint32_t Bs[NSTAGE * B_ST_WORDS];  // 15360 B

    const int tid  = threadIdx.x;
    const int lane = tid & 31;
    const int warp = tid >> 5;
    const int g    = lane >> 2;
    const int t    = lane & 3;
    const int warpM = warp >> 1;  // 0..1 (64-row slab)
    const int warpN = warp & 1;   // 0..1 (32-col slab)

    const int bm = blockIdx.y * BM;
    const int bn = blockIdx.x * BN;

    const uint32_t as_base = (uint32_t)__cvta_generic_to_shared(As);
    const uint32_t bs_base = (uint32_t)__cvta_generic_to_shared(Bs);

    // copy assignments
    // A: 128 rows x 4 chunks(16B) -> row = tid, chunks 0..3
    const __nv_bfloat16* arow = g_abf + (size_t)(bm + tid) * FEAT;
    // B: 64 rows x 4 chunks -> row = tid&63, chunks cb, cb+1
    const int brow_i = tid & 63;
    const int cb = (tid >> 6) * 2;
    const __nv_bfloat16* brow = g_wbf + (size_t)(bn + brow_i) * FEAT;

    // prologue: issue 3 stages
#pragma unroll
    for (int s = 0; s < NSTAGE; s++) {
        const int kk = s * BK;
        uint32_t ad = as_base + s * (A_ST_WORDS * 4) + tid * 80;
#pragma unroll
        for (int c = 0; c < 4; c++)
            cp_async16(ad + c * 16, arow + kk + c * 8);
        uint32_t bd = bs_base + s * (B_ST_WORDS * 4) + brow_i * 80;
        cp_async16(bd + cb * 16, brow + kk + cb * 8);
        cp_async16(bd + (cb + 1) * 16, brow + kk + (cb + 1) * 8);
        asm volatile("cp.async.commit_group;");
    }

    float acc[4][4][4];
#pragma unroll
    for (int mt = 0; mt < 4; mt++)
#pragma unroll
        for (int nt = 0; nt < 4; nt++)
#pragma unroll
            for (int i = 0; i < 4; i++) acc[mt][nt][i] = 0.0f;

    for (int k0 = 0; k0 < NSLAB; k0++) {
        asm volatile("cp.async.wait_group 2;");
        __syncthreads();

        const int st = k0 % NSTAGE;
        const uint32_t* Asm = As + st * A_ST_WORDS;
        const uint32_t* Bsm = Bs + st * B_ST_WORDS;

#pragma unroll
        for (int ks = 0; ks < 2; ks++) {
            const int ko = ks * 8;
            uint32_t bf[4][2];
#pragma unroll
            for (int nt = 0; nt < 4; nt++) {
                const int r0 = (warpN * 32 + nt * 8 + g) * S32 + ko + t;
                bf[nt][0] = Bsm[r0];
                bf[nt][1] = Bsm[r0 + 4];
            }
#pragma unroll
            for (int mt = 0; mt < 4; mt++) {
                const int r0 = (warpM * 64 + mt * 16 + g) * S32 + ko + t;
                uint32_t a0 = Asm[r0];
                uint32_t a1 = Asm[r0 + 8 * S32];
                uint32_t a2 = Asm[r0 + 4];
                uint32_t a3 = Asm[r0 + 8 * S32 + 4];
#pragma unroll
                for (int nt = 0; nt < 4; nt++)
                    mma_bf16(acc[mt][nt], a0, a1, a2, a3, bf[nt][0], bf[nt][1]);
            }
        }
        __syncthreads();

        // refill the stage we just consumed with slab k0+3
        const int nk = k0 + NSTAGE;
        if (nk < NSLAB) {
            const int kk = nk * BK;
            uint32_t ad = as_base + st * (A_ST_WORDS * 4) + tid * 80;
#pragma unroll
            for (int c = 0; c < 4; c++)
                cp_async16(ad + c * 16, arow + kk + c * 8);
            uint32_t bd = bs_base + st * (B_ST_WORDS * 4) + brow_i * 80;
            cp_async16(bd + cb * 16, brow + kk + cb * 8);
            cp_async16(bd + (cb + 1) * 16, brow + kk + (cb + 1) * 8);
        }
        asm volatile("cp.async.commit_group;");
    }

    // ---- epilogue: add bias, write to scratch ----
#pragma unroll
    for (int nt = 0; nt < 4; nt++) {
        const int col = bn + warpN * 32 + nt * 8 + 2 * t;
        const float bias0 = (col < NH) ? tb1[col] : db1[col - NH];
        const float bias1 = (col + 1 < NH) ? tb1[col + 1] : db1[col + 1 - NH];
#pragma unroll
        for (int mt = 0; mt < 4; mt++) {
            const int row = bm + warpM * 64 + mt * 16 + g;
            float2 lo = make_float2(acc[mt][nt][0] + bias0, acc[mt][nt][1] + bias1);
            float2 hi = make_float2(acc[mt][nt][2] + bias0, acc[mt][nt][3] + bias1);
            *reinterpret_cast<float2*>(&g_mid[(size_t)row * MTOT + col]) = lo;
            *reinterpret_cast<float2*>(&g_mid[(size_t)(row + 8) * MTOT + col]) = hi;
        }
    }
}

// ---------------------------------------------------------------------------
// Kernel 2: per-row gating. One warp per batch row.
// ---------------------------------------------------------------------------
__global__ __launch_bounds__(256)
void gating_kernel(const float* __restrict__ tg,
                   const float* __restrict__ tbn,
                   const float* __restrict__ tw2,
                   const float* __restrict__ tb2,
                   const float* __restrict__ lw1,
                   const float* __restrict__ lb1,
                   const float* __restrict__ lw2,
                   const float* __restrict__ lb2,
                   const float* __restrict__ dw2,
                   const float* __restrict__ db2,
                   const float* __restrict__ cw,
                   float* __restrict__ gates_out)  // [BATCH,5]
{
    const int warp = (blockIdx.x * blockDim.x + threadIdx.x) >> 5;
    const int lane = threadIdx.x & 31;
    if (warp >= BATCH) return;

    const float* row = g_mid + (size_t)warp * MTOT;

    // ----- tree nodes: LN + gelu + node logits + softmax(T=0.5) -----
    float pright[NNODES];
#pragma unroll
    for (int n = 0; n < NNODES; n++) {
        float v0 = row[n * 64 + lane];
        float v1 = row[n * 64 + lane + 32];
        float s = v0 + v1;
        float q = v0 * v0 + v1 * v1;
#pragma unroll
        for (int o = 16; o > 0; o >>= 1) {
            s += __shfl_xor_sync(0xffffffffu, s, o);
            q += __shfl_xor_sync(0xffffffffu, q, o);
        }
        float mean = s * (1.0f / 64.0f);
        float var  = q * (1.0f / 64.0f) - mean * mean;
        float rstd = rsqrtf(var + LN_EPS);
        float g0 = gelu_exact((v0 - mean) * rstd * tg[n * 64 + lane] + tbn[n * 64 + lane]);
        float g1 = gelu_exact((v1 - mean) * rstd * tg[n * 64 + lane + 32] + tbn[n * 64 + lane + 32]);
        float z0 = g0 * tw2[n * 128 + lane]      + g1 * tw2[n * 128 + lane + 32];
        float z1 = g0 * tw2[n * 128 + 64 + lane] + g1 * tw2[n * 128 + 64 + lane + 32];
#pragma unroll
        for (int o = 16; o > 0; o >>= 1) {
            z0 += __shfl_xor_sync(0xffffffffu, z0, o);
            z1 += __shfl_xor_sync(0xffffffffu, z1, o);
        }
        z0 += tb2[n * 2 + 0];
        z1 += tb2[n * 2 + 1];
        pright[n] = 1.0f / (1.0f + expf(-2.0f * (z1 - z0)));
    }

    // ----- leaf probabilities -----
    float leaf[NLEAVES];
#pragma unroll
    for (int l = 0; l < NLEAVES; l++) {
        int b2 = (l >> 2) & 1, b1 = (l >> 1) & 1, b0 = l & 1;
        float p2 = b2 ? pright[0] : (1.0f - pright[0]);
        int n1 = 1 + b2;
        float p1 = b1 ? pright[n1] : (1.0f - pright[n1]);
        int n2 = 3 + b2 * 2 + b1;
        float p0 = b0 ? pright[n2] : (1.0f - pright[n2]);
        leaf[l] = p2 * p1 * p0;
    }

    // ----- tree gate head -----
    float t[2 * NSCALE];
#pragma unroll
    for (int j = 0; j < 2 * NSCALE; j++) {
        float a = lb1[j];
#pragma unroll
        for (int l = 0; l < NLEAVES; l++) a += leaf[l] * lw1[j * NLEAVES + l];
        t[j] = gelu_exact(a);
    }
    float tz[NSCALE];
    float tmax = -1e30f;
#pragma unroll
    for (int sIdx = 0; sIdx < NSCALE; sIdx++) {
        float a = lb2[sIdx];
#pragma unroll
        for (int j = 0; j < 2 * NSCALE; j++) a += t[j] * lw2[sIdx * 2 * NSCALE + j];
        tz[sIdx] = a;
        tmax = fmaxf(tmax, a);
    }
    float tsum = 0.0f;
#pragma unroll
    for (int sIdx = 0; sIdx < NSCALE; sIdx++) { tz[sIdx] = expf(tz[sIdx] - tmax); tsum += tz[sIdx]; }
    float tinv = 1.0f / tsum;
#pragma unroll
    for (int sIdx = 0; sIdx < NSCALE; sIdx++) tz[sIdx] *= tinv;

    // ----- direct gate head -----
    float acc5[NSCALE];
#pragma unroll
    for (int sIdx = 0; sIdx < NSCALE; sIdx++) acc5[sIdx] = 0.0f;
#pragma unroll
    for (int r = 0; r < DH / 32; r++) {
        int idx = r * 32 + lane;
        float dg = gelu_exact(row[NH + idx]);
#pragma unroll
        for (int sIdx = 0; sIdx < NSCALE; sIdx++)
            acc5[sIdx] += dg * dw2[sIdx * DH + idx];
    }
#pragma unroll
    for (int sIdx = 0; sIdx < NSCALE; sIdx++) {
        float a = acc5[sIdx];
#pragma unroll
        for (int o = 16; o > 0; o >>= 1) a += __shfl_xor_sync(0xffffffffu, a, o);
        acc5[sIdx] = a + db2[sIdx];
    }
    float dmax = -1e30f;
#pragma unroll
    for (int sIdx = 0; sIdx < NSCALE; sIdx++) dmax = fmaxf(dmax, acc5[sIdx]);
    float dsum = 0.0f;
#pragma unroll
    for (int sIdx = 0; sIdx < NSCALE; sIdx++) { acc5[sIdx] = expf(acc5[sIdx] - dmax); dsum += acc5[sIdx]; }
    float dinv = 1.0f / dsum;
#pragma unroll
    for (int sIdx = 0; sIdx < NSCALE; sIdx++) acc5[sIdx] *= dinv;

    // ----- combine + renormalize -----
    float w = 1.0f / (1.0f + expf(-cw[0]));
    float gg[NSCALE];
    float gs = 0.0f;
#pragma unroll
    for (int sIdx = 0; sIdx < NSCALE; sIdx++) {
        gg[sIdx] = w * tz[sIdx] + (1.0f - w) * acc5[sIdx];
        gs += gg[sIdx];
    }
    float ginv = 1.0f / gs;
    if (lane < NSCALE)
        gates_out[(size_t)warp * NSCALE + lane] = gg[lane] * ginv;
}

// ---------------------------------------------------------------------------
// Kernel 3: combined[b,d] = sum_s gates[b,s] * logits[s,b,d]
// ---------------------------------------------------------------------------
__device__ __forceinline__ float4 ldcs4(const float* p) {
    float4 v;
    asm volatile("ld.global.cs.v4.f32 {%0,%1,%2,%3}, [%4];"
                 : "=f"(v.x), "=f"(v.y), "=f"(v.z), "=f"(v.w) : "l"(p));
    return v;
}
__device__ __forceinline__ void stcs4(float* p, float4 v) {
    asm volatile("st.global.cs.v4.f32 [%0], {%1,%2,%3,%4};"
                 :: "l"(p), "f"(v.x), "f"(v.y), "f"(v.z), "f"(v.w));
}

__global__ __launch_bounds__(256)
void combine_kernel(const float* __restrict__ logits,
                    const float* __restrict__ gates,
                    float* __restrict__ out)
{
    const int b = blockIdx.x;
    const float* gp = gates + (size_t)b * NSCALE;
    float g0 = __ldg(gp + 0), g1 = __ldg(gp + 1), g2 = __ldg(gp + 2),
          g3 = __ldg(gp + 3), g4 = __ldg(gp + 4);

    const size_t rowoff = (size_t)b * DDIM;
    const size_t plane  = (size_t)BATCH * DDIM;

#pragma unroll
    for (int it = 0; it < DDIM / (256 * 4); it++) {
        int col = it * 1024 + threadIdx.x * 4;
        float4 v0 = ldcs4(logits + 0 * plane + rowoff + col);
        float4 v1 = ldcs4(logits + 1 * plane + rowoff + col);
        float4 v2 = ldcs4(logits + 2 * plane + rowoff + col);
        float4 v3 = ldcs4(logits + 3 * plane + rowoff + col);
        float4 v4 = ldcs4(logits + 4 * plane + rowoff + col);
        float4 r;
        r.x = g0 * v0.x + g1 * v1.x + g2 * v2.x + g3 * v3.x + g4 * v4.x;
        r.y = g0 * v0.y + g1 * v1.y + g2 * v2.y + g3 * v3.y + g4 * v4.y;
        r.z = g0 * v0.z + g1 * v1.z + g2 * v2.z + g3 * v3.z + g4 * v4.z;
        r.w = g0 * v0.w + g1 * v1.w + g2 * v2.w + g3 * v3.w + g4 * v4.w;
        stcs4(out + rowoff + col, r);
    }
}

// ---------------------------------------------------------------------------
// Launcher. d_out layout: [combined (8192*4096 f32)] [gates (8192*5 f32)]
// ---------------------------------------------------------------------------
extern "C" void kernel_launch(void* const* d_in, const int* in_sizes, int n_in,
                              void* d_out, int out_size)
{
    const float* features = (const float*)d_in[0];
    const float* logits   = (const float*)d_in[1];
    const float* tw1      = (const float*)d_in[2];
    const float* tb1      = (const float*)d_in[3];
    const float* tg       = (const float*)d_in[4];
    const float* tbn      = (const float*)d_in[5];
    const float* tw2      = (const float*)d_in[6];
    const float* tb2      = (const float*)d_in[7];
    const float* lw1      = (const float*)d_in[8];
    const float* lb1      = (const float*)d_in[9];
    const float* lw2      = (const float*)d_in[10];
    const float* lb2      = (const float*)d_in[11];
    const float* dw1      = (const float*)d_in[12];
    const float* db1      = (const float*)d_in[13];
    const float* dw2      = (const float*)d_in[14];
    const float* db2      = (const float*)d_in[15];
    const float* cw       = (const float*)d_in[16];

    float* out = (float*)d_out;
    float* gates_out = out + (size_t)BATCH * DDIM;

    const int conv_total = A_VEC4 + W_VEC4;
    convert_kernel<<<(conv_total + 255) / 256, 256>>>(features, tw1, dw1);

    dim3 gemm_grid(MTOT / BN, BATCH / BM);  // (11, 64)
    gemm_tc_kernel<<<gemm_grid, 128>>>(tb1, db1);

    gating_kernel<<<BATCH / 8, 256>>>(tg, tbn, tw2, tb2, lw1, lb1, lw2, lb2,
                                      dw2, db2, cw, gates_out);

    combine_kernel<<<BATCH, 256>>>(logits, gates_out, out);
}

// round 11
// speedup vs baseline: 1.0178x; 1.0178x over previous
#include <cuda_runtime.h>
#include <cuda_bf16.h>
#include <math.h>
#include <stdint.h>

// Problem constants
#define BATCH   8192
#define FEAT    1024
#define DDIM    4096
#define NSCALE  5
#define NNODES  7
#define NLEAVES 8
#define HID     64
#define NH      448   // NNODES*HID
#define DH      256   // FEAT/4
#define MTOT    704   // NH + DH
#define LN_EPS  1e-5f

// Scratch
__device__ float g_mid[BATCH * MTOT];                 // GEMM output (pre-activation)
__device__ __nv_bfloat16 g_abf[BATCH * FEAT];         // features in bf16
__device__ __nv_bfloat16 g_wbf[MTOT * FEAT];          // fused weights [tw1; dw1] in bf16

__device__ __forceinline__ float gelu_exact(float x) {
    return 0.5f * x * (1.0f + erff(x * 0.70710678118654752440f));
}

__device__ __forceinline__ void mma_bf16(float c[4],
                                         uint32_t a0, uint32_t a1, uint32_t a2, uint32_t a3,
                                         uint32_t b0, uint32_t b1) {
    asm volatile(
        "mma.sync.aligned.m16n8k16.row.col.f32.bf16.bf16.f32 "
        "{%0,%1,%2,%3}, {%4,%5,%6,%7}, {%8,%9}, {%0,%1,%2,%3};\n"
        : "+f"(c[0]), "+f"(c[1]), "+f"(c[2]), "+f"(c[3])
        : "r"(a0), "r"(a1), "r"(a2), "r"(a3), "r"(b0), "r"(b1));
}

__device__ __forceinline__ void cp_async16(uint32_t smem_addr, const void* gptr) {
    asm volatile("cp.async.cg.shared.global [%0], [%1], 16;"
                 :: "r"(smem_addr), "l"(gptr));
}

// ---------------------------------------------------------------------------
// Kernel 0: convert features + fused weights to bf16
// ---------------------------------------------------------------------------
#define A_VEC4 (BATCH * FEAT / 4)      // 2,097,152
#define W_VEC4 (MTOT * FEAT / 4)       // 180,224

__global__ __launch_bounds__(256)
void convert_kernel(const float* __restrict__ feat,
                    const float* __restrict__ tw1,
                    const float* __restrict__ dw1)
{
    int idx = blockIdx.x * 256 + threadIdx.x;
    if (idx < A_VEC4) {
        float4 v = *reinterpret_cast<const float4*>(feat + (size_t)idx * 4);
        __nv_bfloat162 lo = __floats2bfloat162_rn(v.x, v.y);
        __nv_bfloat162 hi = __floats2bfloat162_rn(v.z, v.w);
        uint2 r = make_uint2(*reinterpret_cast<uint32_t*>(&lo),
                             *reinterpret_cast<uint32_t*>(&hi));
        *reinterpret_cast<uint2*>(&g_abf[(size_t)idx * 4]) = r;
    } else if (idx < A_VEC4 + W_VEC4) {
        int w4 = idx - A_VEC4;
        size_t e = (size_t)w4 * 4;
        int row = (int)(e >> 10);
        const float* src = (row < NH) ? (tw1 + e) : (dw1 + e - (size_t)NH * FEAT);
        float4 v = *reinterpret_cast<const float4*>(src);
        __nv_bfloat162 lo = __floats2bfloat162_rn(v.x, v.y);
        __nv_bfloat162 hi = __floats2bfloat162_rn(v.z, v.w);
        uint2 r = make_uint2(*reinterpret_cast<uint32_t*>(&lo),
                             *reinterpret_cast<uint32_t*>(&hi));
        *reinterpret_cast<uint2*>(&g_wbf[e]) = r;
    }
}

// ---------------------------------------------------------------------------
// Kernel 1: cp.async-pipelined bf16 tensor-core GEMM (single-sync multistage)
//   C[b, m] = sum_f A[b,f] * W(m,f) + bias(m), into g_mid.
// BM=128, BN=64, BK=32, 128 threads, 4 warps (2M x 2N), warp tile 64x32.
// 3 stages, ONE __syncthreads per slab, copies issued BEFORE compute:
//   prologue: issue slabs 0,1
//   iter k:   wait_group 1 (slab k landed) -> sync -> issue slab k+2 into
//             slot (k+2)%3 (freed by slab k-1, safe by this sync) -> compute k
// Smem rows: 32 bf16 = 64 B data padded to 80 B -> conflict-free scalar LDS
// fragments AND 16B-aligned rows for cp.async.
// ---------------------------------------------------------------------------
#define BM 128
#define BN 64
#define BK 32
#define S32 20
#define NSTAGE 3
#define A_ST_WORDS (BM * S32)   // 2560 words = 10240 B
#define B_ST_WORDS (BN * S32)   // 1280 words =  5120 B
#define NSLAB (FEAT / BK)       // 32

__global__ __launch_bounds__(128, 4)
void gemm_tc_kernel(const float* __restrict__ tb1,
                    const float* __restrict__ db1)
{
    __shared__ __align__(16) uint32_t As[NSTAGE * A_ST_WORDS];  // 30720 B
    __shared__ __align__(16) uint32_t Bs[NSTAGE * B_ST_WORDS];  // 15360 B

    const int tid  = threadIdx.x;
    const int lane = tid & 31;
    const int warp = tid >> 5;
    const int g    = lane >> 2;
    const int t    = lane & 3;
    const int warpM = warp >> 1;  // 0..1 (64-row slab)
    const int warpN = warp & 1;   // 0..1 (32-col slab)

    const int bm = blockIdx.y * BM;
    const int bn = blockIdx.x * BN;

    const uint32_t as_base = (uint32_t)__cvta_generic_to_shared(As);
    const uint32_t bs_base = (uint32_t)__cvta_generic_to_shared(Bs);

    // copy assignments
    // A: 128 rows x 4 chunks(16B) -> row = tid, chunks 0..3
    const __nv_bfloat16* arow = g_abf + (size_t)(bm + tid) * FEAT;
    // B: 64 rows x 4 chunks -> row = tid&63, chunks cb, cb+1
    const int brow_i = tid & 63;
    const int cb = (tid >> 6) * 2;
    const __nv_bfloat16* brow = g_wbf + (size_t)(bn + brow_i) * FEAT;

    const uint32_t a_dst = as_base + tid * 80;
    const uint32_t b_dst = bs_base + brow_i * 80;

    // prologue: issue 2 stages
#pragma unroll
    for (int s = 0; s < 2; s++) {
        const int kk = s * BK;
        uint32_t ad = a_dst + s * (A_ST_WORDS * 4);
#pragma unroll
        for (int c = 0; c < 4; c++)
            cp_async16(ad + c * 16, arow + kk + c * 8);
        uint32_t bd = b_dst + s * (B_ST_WORDS * 4);
        cp_async16(bd + cb * 16, brow + kk + cb * 8);
        cp_async16(bd + (cb + 1) * 16, brow + kk + (cb + 1) * 8);
        asm volatile("cp.async.commit_group;");
    }

    float acc[4][4][4];
#pragma unroll
    for (int mt = 0; mt < 4; mt++)
#pragma unroll
        for (int nt = 0; nt < 4; nt++)
#pragma unroll
            for (int i = 0; i < 4; i++) acc[mt][nt][i] = 0.0f;

    for (int k0 = 0; k0 < NSLAB; k0++) {
        asm volatile("cp.async.wait_group 1;");
        __syncthreads();

        // issue slab k0+2 into the slot freed by slab k0-1 (safe by sync above)
        const int nk = k0 + 2;
        if (nk < NSLAB) {
            const int st_w = nk % NSTAGE;
            const int kk = nk * BK;
            uint32_t ad = a_dst + st_w * (A_ST_WORDS * 4);
#pragma unroll
            for (int c = 0; c < 4; c++)
                cp_async16(ad + c * 16, arow + kk + c * 8);
            uint32_t bd = b_dst + st_w * (B_ST_WORDS * 4);
            cp_async16(bd + cb * 16, brow + kk + cb * 8);
            cp_async16(bd + (cb + 1) * 16, brow + kk + (cb + 1) * 8);
        }
        asm volatile("cp.async.commit_group;");

        // compute slab k0 (overlaps with the copies just issued)
        const int st = k0 % NSTAGE;
        const uint32_t* Asm = As + st * A_ST_WORDS;
        const uint32_t* Bsm = Bs + st * B_ST_WORDS;

#pragma unroll
        for (int ks = 0; ks < 2; ks++) {
            const int ko = ks * 8;
            uint32_t bf[4][2];
#pragma unroll
            for (int nt = 0; nt < 4; nt++) {
                const int r0 = (warpN * 32 + nt * 8 + g) * S32 + ko + t;
                bf[nt][0] = Bsm[r0];
                bf[nt][1] = Bsm[r0 + 4];
            }
#pragma unroll
            for (int mt = 0; mt < 4; mt++) {
                const int r0 = (warpM * 64 + mt * 16 + g) * S32 + ko + t;
                uint32_t a0 = Asm[r0];
                uint32_t a1 = Asm[r0 + 8 * S32];
                uint32_t a2 = Asm[r0 + 4];
                uint32_t a3 = Asm[r0 + 8 * S32 + 4];
#pragma unroll
                for (int nt = 0; nt < 4; nt++)
                    mma_bf16(acc[mt][nt], a0, a1, a2, a3, bf[nt][0], bf[nt][1]);
            }
        }
    }

    // ---- epilogue: add bias, write to scratch ----
#pragma unroll
    for (int nt = 0; nt < 4; nt++) {
        const int col = bn + warpN * 32 + nt * 8 + 2 * t;
        const float bias0 = (col < NH) ? tb1[col] : db1[col - NH];
        const float bias1 = (col + 1 < NH) ? tb1[col + 1] : db1[col + 1 - NH];
#pragma unroll
        for (int mt = 0; mt < 4; mt++) {
            const int row = bm + warpM * 64 + mt * 16 + g;
            float2 lo = make_float2(acc[mt][nt][0] + bias0, acc[mt][nt][1] + bias1);
            float2 hi = make_float2(acc[mt][nt][2] + bias0, acc[mt][nt][3] + bias1);
            *reinterpret_cast<float2*>(&g_mid[(size_t)row * MTOT + col]) = lo;
            *reinterpret_cast<float2*>(&g_mid[(size_t)(row + 8) * MTOT + col]) = hi;
        }
    }
}

// ---------------------------------------------------------------------------
// Kernel 2 (fused): per-row gating (warp 0) + combine streaming (all warps).
// One block per batch row.
// ---------------------------------------------------------------------------
__device__ __forceinline__ float4 ldcs4(const float* p) {
    float4 v;
    asm volatile("ld.global.cs.v4.f32 {%0,%1,%2,%3}, [%4];"
                 : "=f"(v.x), "=f"(v.y), "=f"(v.z), "=f"(v.w) : "l"(p));
    return v;
}
__device__ __forceinline__ void stcs4(float* p, float4 v) {
    asm volatile("st.global.cs.v4.f32 [%0], {%1,%2,%3,%4};"
                 :: "l"(p), "f"(v.x), "f"(v.y), "f"(v.z), "f"(v.w));
}

__global__ __launch_bounds__(256)
void combine_kernel(const float* __restrict__ logits,
                    float* __restrict__ out,
                    float* __restrict__ gates_out,
                    const float* __restrict__ tg,
                    const float* __restrict__ tbn,
                    const float* __restrict__ tw2,
                    const float* __restrict__ tb2,
                    const float* __restrict__ lw1,
                    const float* __restrict__ lb1,
                    const float* __restrict__ lw2,
                    const float* __restrict__ lb2,
                    const float* __restrict__ dw2,
                    const float* __restrict__ db2,
                    const float* __restrict__ cw)
{
    __shared__ float sg[NSCALE];
    const int b = blockIdx.x;
    const int tid = threadIdx.x;

    if (tid < 32) {
        const int lane = tid;
        const float* row = g_mid + (size_t)b * MTOT;

        // ----- tree nodes: LN + gelu + node logits + softmax(T=0.5) -----
        float pright[NNODES];
#pragma unroll
        for (int n = 0; n < NNODES; n++) {
            float v0 = row[n * 64 + lane];
            float v1 = row[n * 64 + lane + 32];
            float s = v0 + v1;
            float q = v0 * v0 + v1 * v1;
#pragma unroll
            for (int o = 16; o > 0; o >>= 1) {
                s += __shfl_xor_sync(0xffffffffu, s, o);
                q += __shfl_xor_sync(0xffffffffu, q, o);
            }
            float mean = s * (1.0f / 64.0f);
            float var  = q * (1.0f / 64.0f) - mean * mean;
            float rstd = rsqrtf(var + LN_EPS);
            float g0 = gelu_exact((v0 - mean) * rstd * tg[n * 64 + lane] + tbn[n * 64 + lane]);
            float g1 = gelu_exact((v1 - mean) * rstd * tg[n * 64 + lane + 32] + tbn[n * 64 + lane + 32]);
            float z0 = g0 * tw2[n * 128 + lane]      + g1 * tw2[n * 128 + lane + 32];
            float z1 = g0 * tw2[n * 128 + 64 + lane] + g1 * tw2[n * 128 + 64 + lane + 32];
#pragma unroll
            for (int o = 16; o > 0; o >>= 1) {
                z0 += __shfl_xor_sync(0xffffffffu, z0, o);
                z1 += __shfl_xor_sync(0xffffffffu, z1, o);
            }
            z0 += tb2[n * 2 + 0];
            z1 += tb2[n * 2 + 1];
            pright[n] = 1.0f / (1.0f + expf(-2.0f * (z1 - z0)));
        }

        // ----- leaf probabilities -----
        float leaf[NLEAVES];
#pragma unroll
        for (int l = 0; l < NLEAVES; l++) {
            int b2 = (l >> 2) & 1, b1 = (l >> 1) & 1, b0 = l & 1;
            float p2 = b2 ? pright[0] : (1.0f - pright[0]);
            int n1 = 1 + b2;
            float p1 = b1 ? pright[n1] : (1.0f - pright[n1]);
            int n2 = 3 + b2 * 2 + b1;
            float p0 = b0 ? pright[n2] : (1.0f - pright[n2]);
            leaf[l] = p2 * p1 * p0;
        }

        // ----- tree gate head -----
        float t[2 * NSCALE];
#pragma unroll
        for (int j = 0; j < 2 * NSCALE; j++) {
            float a = lb1[j];
#pragma unroll
            for (int l = 0; l < NLEAVES; l++) a += leaf[l] * lw1[j * NLEAVES + l];
            t[j] = gelu_exact(a);
        }
        float tz[NSCALE];
        float tmax = -1e30f;
#pragma unroll
        for (int sIdx = 0; sIdx < NSCALE; sIdx++) {
            float a = lb2[sIdx];
#pragma unroll
            for (int j = 0; j < 2 * NSCALE; j++) a += t[j] * lw2[sIdx * 2 * NSCALE + j];
            tz[sIdx] = a;
            tmax = fmaxf(tmax, a);
        }
        float tsum = 0.0f;
#pragma unroll
        for (int sIdx = 0; sIdx < NSCALE; sIdx++) { tz[sIdx] = expf(tz[sIdx] - tmax); tsum += tz[sIdx]; }
        float tinv = 1.0f / tsum;
#pragma unroll
        for (int sIdx = 0; sIdx < NSCALE; sIdx++) tz[sIdx] *= tinv;

        // ----- direct gate head -----
        float acc5[NSCALE];
#pragma unroll
        for (int sIdx = 0; sIdx < NSCALE; sIdx++) acc5[sIdx] = 0.0f;
#pragma unroll
        for (int r = 0; r < DH / 32; r++) {
            int idx = r * 32 + lane;
            float dg = gelu_exact(row[NH + idx]);
#pragma unroll
            for (int sIdx = 0; sIdx < NSCALE; sIdx++)
                acc5[sIdx] += dg * dw2[sIdx * DH + idx];
        }
#pragma unroll
        for (int sIdx = 0; sIdx < NSCALE; sIdx++) {
            float a = acc5[sIdx];
#pragma unroll
            for (int o = 16; o > 0; o >>= 1) a += __shfl_xor_sync(0xffffffffu, a, o);
            acc5[sIdx] = a + db2[sIdx];
        }
        float dmax = -1e30f;
#pragma unroll
        for (int sIdx = 0; sIdx < NSCALE; sIdx++) dmax = fmaxf(dmax, acc5[sIdx]);
        float dsum = 0.0f;
#pragma unroll
        for (int sIdx = 0; sIdx < NSCALE; sIdx++) { acc5[sIdx] = expf(acc5[sIdx] - dmax); dsum += acc5[sIdx]; }
        float dinv = 1.0f / dsum;
#pragma unroll
        for (int sIdx = 0; sIdx < NSCALE; sIdx++) acc5[sIdx] *= dinv;

        // ----- combine + renormalize -----
        float w = 1.0f / (1.0f + expf(-cw[0]));
        float gg[NSCALE];
        float gs = 0.0f;
#pragma unroll
        for (int sIdx = 0; sIdx < NSCALE; sIdx++) {
            gg[sIdx] = w * tz[sIdx] + (1.0f - w) * acc5[sIdx];
            gs += gg[sIdx];
        }
        float ginv = 1.0f / gs;
        if (lane < NSCALE) {
            float v = gg[lane] * ginv;
            sg[lane] = v;
            gates_out[(size_t)b * NSCALE + lane] = v;
        }
    }
    __syncthreads();

    const float g0 = sg[0], g1 = sg[1], g2 = sg[2], g3 = sg[3], g4 = sg[4];
    const size_t rowoff = (size_t)b * DDIM;
    const size_t plane  = (size_t)BATCH * DDIM;

#pragma unroll
    for (int it = 0; it < DDIM / (256 * 4); it++) {
        int col = it * 1024 + tid * 4;
        float4 v0 = ldcs4(logits + 0 * plane + rowoff + col);
        float4 v1 = ldcs4(logits + 1 * plane + rowoff + col);
        float4 v2 = ldcs4(logits + 2 * plane + rowoff + col);
        float4 v3 = ldcs4(logits + 3 * plane + rowoff + col);
        float4 v4 = ldcs4(logits + 4 * plane + rowoff + col);
        float4 r;
        r.x = g0 * v0.x + g1 * v1.x + g2 * v2.x + g3 * v3.x + g4 * v4.x;
        r.y = g0 * v0.y + g1 * v1.y + g2 * v2.y + g3 * v3.y + g4 * v4.y;
        r.z = g0 * v0.z + g1 * v1.z + g2 * v2.z + g3 * v3.z + g4 * v4.z;
        r.w = g0 * v0.w + g1 * v1.w + g2 * v2.w + g3 * v3.w + g4 * v4.w;
        stcs4(out + rowoff + col, r);
    }
}

// ---------------------------------------------------------------------------
// Launcher. d_out layout: [combined (8192*4096 f32)] [gates (8192*5 f32)]
// ---------------------------------------------------------------------------
extern "C" void kernel_launch(void* const* d_in, const int* in_sizes, int n_in,
                              void* d_out, int out_size)
{
    const float* features = (const float*)d_in[0];
    const float* logits   = (const float*)d_in[1];
    const float* tw1      = (const float*)d_in[2];
    const float* tb1      = (const float*)d_in[3];
    const float* tg       = (const float*)d_in[4];
    const float* tbn      = (const float*)d_in[5];
    const float* tw2      = (const float*)d_in[6];
    const float* tb2      = (const float*)d_in[7];
    const float* lw1      = (const float*)d_in[8];
    const float* lb1      = (const float*)d_in[9];
    const float* lw2      = (const float*)d_in[10];
    const float* lb2      = (const float*)d_in[11];
    const float* dw1      = (const float*)d_in[12];
    const float* db1      = (const float*)d_in[13];
    const float* dw2      = (const float*)d_in[14];
    const float* db2      = (const float*)d_in[15];
    const float* cw       = (const float*)d_in[16];

    float* out = (float*)d_out;
    float* gates_out = out + (size_t)BATCH * DDIM;

    const int conv_total = A_VEC4 + W_VEC4;
    convert_kernel<<<(conv_total + 255) / 256, 256>>>(features, tw1, dw1);

    dim3 gemm_grid(MTOT / BN, BATCH / BM);  // (11, 64)
    gemm_tc_kernel<<<gemm_grid, 128>>>(tb1, db1);

    combine_kernel<<<BATCH, 256>>>(logits, out, gates_out,
                                   tg, tbn, tw2, tb2, lw1, lb1, lw2, lb2,
                                   dw2, db2, cw);
}

// round 15
// speedup vs baseline: 1.1842x; 1.1635x over previous
#include <cuda_runtime.h>
#include <cuda_bf16.h>
#include <math.h>
#include <stdint.h>

// Problem constants
#define BATCH   8192
#define FEAT    1024
#define DDIM    4096
#define NSCALE  5
#define NNODES  7
#define NLEAVES 8
#define HID     64
#define NH      448   // NNODES*HID
#define DH      256   // FEAT/4
#define MTOT    704   // NH + DH
#define LN_EPS  1e-5f

// Scratch
__device__ float g_mid[BATCH * MTOT];                 // GEMM output (pre-activation)
__device__ __nv_bfloat16 g_abf[BATCH * FEAT];         // features in bf16
__device__ __nv_bfloat16 g_wbf[MTOT * FEAT];          // fused weights [tw1; dw1] in bf16

__device__ __forceinline__ float gelu_exact(float x) {
    return 0.5f * x * (1.0f + erff(x * 0.70710678118654752440f));
}

__device__ __forceinline__ void mma_bf16(float c[4],
                                         uint32_t a0, uint32_t a1, uint32_t a2, uint32_t a3,
                                         uint32_t b0, uint32_t b1) {
    asm volatile(
        "mma.sync.aligned.m16n8k16.row.col.f32.bf16.bf16.f32 "
        "{%0,%1,%2,%3}, {%4,%5,%6,%7}, {%8,%9}, {%0,%1,%2,%3};\n"
        : "+f"(c[0]), "+f"(c[1]), "+f"(c[2]), "+f"(c[3])
        : "r"(a0), "r"(a1), "r"(a2), "r"(a3), "r"(b0), "r"(b1));
}

__device__ __forceinline__ void ldmatrix_x4(uint32_t& r0, uint32_t& r1,
                                            uint32_t& r2, uint32_t& r3,
                                            uint32_t addr) {
    asm volatile("ldmatrix.sync.aligned.m8n8.x4.shared.b16 {%0,%1,%2,%3}, [%4];"
                 : "=r"(r0), "=r"(r1), "=r"(r2), "=r"(r3) : "r"(addr));
}

__device__ __forceinline__ void cp_async16(uint32_t smem_addr, const void* gptr) {
    asm volatile("cp.async.cg.shared.global [%0], [%1], 16;"
                 :: "r"(smem_addr), "l"(gptr));
}

// ---------------------------------------------------------------------------
// Kernel 0: convert features + fused weights to bf16
// ---------------------------------------------------------------------------
#define A_VEC4 (BATCH * FEAT / 4)      // 2,097,152
#define W_VEC4 (MTOT * FEAT / 4)       // 180,224

__global__ __launch_bounds__(256)
void convert_kernel(const float* __restrict__ feat,
                    const float* __restrict__ tw1,
                    const float* __restrict__ dw1)
{
    int idx = blockIdx.x * 256 + threadIdx.x;
    if (idx < A_VEC4) {
        float4 v = *reinterpret_cast<const float4*>(feat + (size_t)idx * 4);
        __nv_bfloat162 lo = __floats2bfloat162_rn(v.x, v.y);
        __nv_bfloat162 hi = __floats2bfloat162_rn(v.z, v.w);
        uint2 r = make_uint2(*reinterpret_cast<uint32_t*>(&lo),
                             *reinterpret_cast<uint32_t*>(&hi));
        *reinterpret_cast<uint2*>(&g_abf[(size_t)idx * 4]) = r;
    } else if (idx < A_VEC4 + W_VEC4) {
        int w4 = idx - A_VEC4;
        size_t e = (size_t)w4 * 4;
        int row = (int)(e >> 10);
        const float* src = (row < NH) ? (tw1 + e) : (dw1 + e - (size_t)NH * FEAT);
        float4 v = *reinterpret_cast<const float4*>(src);
        __nv_bfloat162 lo = __floats2bfloat162_rn(v.x, v.y);
        __nv_bfloat162 hi = __floats2bfloat162_rn(v.z, v.w);
        uint2 r = make_uint2(*reinterpret_cast<uint32_t*>(&lo),
                             *reinterpret_cast<uint32_t*>(&hi));
        *reinterpret_cast<uint2*>(&g_wbf[e]) = r;
    }
}

// ---------------------------------------------------------------------------
// Kernel 1: bf16 HMMA GEMM, ldmatrix fragments, cp.async 3-stage pipeline.
//   C[b, m] = sum_f A[b,f] * W(m,f) + bias(m), into g_mid.
// BM=128, BN=64, BK=64 (128 B rows = one SW128 atom), 256 threads,
// 8 warps (2M x 4N), warp tile 64x16.
// Smem: SW128-swizzled 128 B rows; cp.async 16B chunks; ldmatrix.x4 reads.
// Per warp per k16-step: 1 B-ldmatrix.x4 + 4 A-ldmatrix.x4 + 8 MMA.
// Single-sync multistage (verified schedule): prologue slabs 0,1;
// iter k: wait_group 1 -> sync -> issue slab k+2 -> commit -> compute k.
// ---------------------------------------------------------------------------
#define BM 128
#define BN 64
#define BK 64
#define NSTAGE 3
#define A_STB (BM * 128)          // 16384 B per stage
#define B_STB (BN * 128)          //  8192 B per stage
#define ST_B  (A_STB + B_STB)     // 24576 B per stage
#define GEMM_SMEM (NSTAGE * ST_B) // 73728 B
#define NSLAB (FEAT / BK)         // 16

__device__ __forceinline__ void gemm_load_slab(uint32_t smem_base, int slab,
                                               int stage, int tid, int bm, int bn) {
    const int kk = slab * BK;
    const uint32_t abase = smem_base + stage * ST_B;
    const uint32_t bbase = abase + A_STB;
    // A: 128 rows x 8 x 16B chunks = 1024 chunks / 256 threads
#pragma unroll
    for (int i = 0; i < 4; i++) {
        int idx = i * 256 + tid;
        int row = idx >> 3;
        int c   = idx & 7;
        uint32_t off = (uint32_t)(row * 128 + c * 16);
        uint32_t sw  = off ^ ((off >> 3) & 0x70);
        cp_async16(abase + sw, g_abf + (size_t)(bm + row) * FEAT + kk + c * 8);
    }
    // B: 64 rows x 8 chunks = 512 chunks
#pragma unroll
    for (int i = 0; i < 2; i++) {
        int idx = i * 256 + tid;
        int row = idx >> 3;
        int c   = idx & 7;
        uint32_t off = (uint32_t)(row * 128 + c * 16);
        uint32_t sw  = off ^ ((off >> 3) & 0x70);
        cp_async16(bbase + sw, g_wbf + (size_t)(bn + row) * FEAT + kk + c * 8);
    }
}

__global__ __launch_bounds__(256)
void gemm_tc_kernel(const float* __restrict__ tb1,
                    const float* __restrict__ db1)
{
    extern __shared__ __align__(128) char smem[];
    const uint32_t smem_base = (uint32_t)__cvta_generic_to_shared(smem);

    const int tid  = threadIdx.x;
    const int lane = tid & 31;
    const int warp = tid >> 5;
    const int g    = lane >> 2;
    const int t    = lane & 3;
    const int warpM = warp >> 2;  // 0..1 -> 64 rows
    const int warpN = warp & 3;   // 0..3 -> 16 cols

    const int bm = blockIdx.y * BM;
    const int bn = blockIdx.x * BN;

    // ldmatrix lane->row/k mapping (m = lane>>3: row += (m&1)*8, kbyte += (m>>1)*16)
    const int lr   = lane & 7;
    const int m01  = (lane >> 3) & 1;
    const int mk16 = (lane >> 4) * 16;      // 0 or 16 bytes
    const int a_row = warpM * 64 + m01 * 8 + lr;   // + mt*16 (doesn't change row&7)
    const int b_row = warpN * 16 + m01 * 8 + lr;
    const uint32_t xa = (uint32_t)((a_row & 7) << 4);
    const uint32_t xb = (uint32_t)((b_row & 7) << 4);

    // prologue: slabs 0,1
#pragma unroll
    for (int s = 0; s < 2; s++) {
        gemm_load_slab(smem_base, s, s, tid, bm, bn);
        asm volatile("cp.async.commit_group;");
    }

    float acc[4][2][4];
#pragma unroll
    for (int mt = 0; mt < 4; mt++)
#pragma unroll
        for (int nt = 0; nt < 2; nt++)
#pragma unroll
            for (int i = 0; i < 4; i++) acc[mt][nt][i] = 0.0f;

    for (int k0 = 0; k0 < NSLAB; k0++) {
        asm volatile("cp.async.wait_group 1;");
        __syncthreads();

        // issue slab k0+2 into slot freed by slab k0-1
        const int nk = k0 + 2;
        if (nk < NSLAB)
            gemm_load_slab(smem_base, nk, nk % NSTAGE, tid, bm, bn);
        asm volatile("cp.async.commit_group;");

        // compute slab k0
        const int st = k0 % NSTAGE;
        const uint32_t abase = smem_base + st * ST_B;
        const uint32_t bbase = abase + A_STB;
        const uint32_t a_base_addr = abase + (uint32_t)(a_row * 128);
        const uint32_t b_base_addr = bbase + (uint32_t)(b_row * 128);

#pragma unroll
        for (int q = 0; q < 4; q++) {
            const uint32_t kb = (uint32_t)(q * 32 + mk16);
            uint32_t br0, br1, br2, br3;
            ldmatrix_x4(br0, br1, br2, br3, b_base_addr + (kb ^ xb));
#pragma unroll
            for (int mt = 0; mt < 4; mt++) {
                uint32_t a0, a1, a2, a3;
                ldmatrix_x4(a0, a1, a2, a3,
                            a_base_addr + (uint32_t)(mt * 16 * 128) + (kb ^ xa));
                mma_bf16(acc[mt][0], a0, a1, a2, a3, br0, br2);
                mma_bf16(acc[mt][1], a0, a1, a2, a3, br1, br3);
            }
        }
    }

    // ---- epilogue: add bias, write to scratch ----
#pragma unroll
    for (int nt = 0; nt < 2; nt++) {
        const int col = bn + warpN * 16 + nt * 8 + 2 * t;
        const float bias0 = (col < NH) ? tb1[col] : db1[col - NH];
        const float bias1 = (col + 1 < NH) ? tb1[col + 1] : db1[col + 1 - NH];
#pragma unroll
        for (int mt = 0; mt < 4; mt++) {
            const int row = bm + warpM * 64 + mt * 16 + g;
            float2 lo = make_float2(acc[mt][nt][0] + bias0, acc[mt][nt][1] + bias1);
            float2 hi = make_float2(acc[mt][nt][2] + bias0, acc[mt][nt][3] + bias1);
            *reinterpret_cast<float2*>(&g_mid[(size_t)row * MTOT + col]) = lo;
            *reinterpret_cast<float2*>(&g_mid[(size_t)(row + 8) * MTOT + col]) = hi;
        }
    }
}

// ---------------------------------------------------------------------------
// Kernel 2 (fused): per-row gating (warp 0) + combine streaming (all warps).
// ---------------------------------------------------------------------------
__device__ __forceinline__ float4 ldcs4(const float* p) {
    float4 v;
    asm volatile("ld.global.cs.v4.f32 {%0,%1,%2,%3}, [%4];"
                 : "=f"(v.x), "=f"(v.y), "=f"(v.z), "=f"(v.w) : "l"(p));
    return v;
}
__device__ __forceinline__ void stcs4(float* p, float4 v) {
    asm volatile("st.global.cs.v4.f32 [%0], {%1,%2,%3,%4};"
                 :: "l"(p), "f"(v.x), "f"(v.y), "f"(v.z), "f"(v.w));
}

__global__ __launch_bounds__(256)
void combine_kernel(const float* __restrict__ logits,
                    float* __restrict__ out,
                    float* __restrict__ gates_out,
                    const float* __restrict__ tg,
                    const float* __restrict__ tbn,
                    const float* __restrict__ tw2,
                    const float* __restrict__ tb2,
                    const float* __restrict__ lw1,
                    const float* __restrict__ lb1,
                    const float* __restrict__ lw2,
                    const float* __restrict__ lb2,
                    const float* __restrict__ dw2,
                    const float* __restrict__ db2,
                    const float* __restrict__ cw)
{
    __shared__ float sg[NSCALE];
    const int b = blockIdx.x;
    const int tid = threadIdx.x;

    if (tid < 32) {
        const int lane = tid;
        const float* row = g_mid + (size_t)b * MTOT;

        float pright[NNODES];
#pragma unroll
        for (int n = 0; n < NNODES; n++) {
            float v0 = row[n * 64 + lane];
            float v1 = row[n * 64 + lane + 32];
            float s = v0 + v1;
            float q = v0 * v0 + v1 * v1;
#pragma unroll
            for (int o = 16; o > 0; o >>= 1) {
                s += __shfl_xor_sync(0xffffffffu, s, o);
                q += __shfl_xor_sync(0xffffffffu, q, o);
            }
            float mean = s * (1.0f / 64.0f);
            float var  = q * (1.0f / 64.0f) - mean * mean;
            float rstd = rsqrtf(var + LN_EPS);
            float g0 = gelu_exact((v0 - mean) * rstd * tg[n * 64 + lane] + tbn[n * 64 + lane]);
            float g1 = gelu_exact((v1 - mean) * rstd * tg[n * 64 + lane + 32] + tbn[n * 64 + lane + 32]);
            float z0 = g0 * tw2[n * 128 + lane]      + g1 * tw2[n * 128 + lane + 32];
            float z1 = g0 * tw2[n * 128 + 64 + lane] + g1 * tw2[n * 128 + 64 + lane + 32];
#pragma unroll
            for (int o = 16; o > 0; o >>= 1) {
                z0 += __shfl_xor_sync(0xffffffffu, z0, o);
                z1 += __shfl_xor_sync(0xffffffffu, z1, o);
            }
            z0 += tb2[n * 2 + 0];
            z1 += tb2[n * 2 + 1];
            pright[n] = 1.0f / (1.0f + expf(-2.0f * (z1 - z0)));
        }

        float leaf[NLEAVES];
#pragma unroll
        for (int l = 0; l < NLEAVES; l++) {
            int b2 = (l >> 2) & 1, b1 = (l >> 1) & 1, b0 = l & 1;
            float p2 = b2 ? pright[0] : (1.0f - pright[0]);
            int n1 = 1 + b2;
            float p1 = b1 ? pright[n1] : (1.0f - pright[n1]);
            int n2 = 3 + b2 * 2 + b1;
            float p0 = b0 ? pright[n2] : (1.0f - pright[n2]);
            leaf[l] = p2 * p1 * p0;
        }

        float t[2 * NSCALE];
#pragma unroll
        for (int j = 0; j < 2 * NSCALE; j++) {
            float a = lb1[j];
#pragma unroll
            for (int l = 0; l < NLEAVES; l++) a += leaf[l] * lw1[j * NLEAVES + l];
            t[j] = gelu_exact(a);
        }
        float tz[NSCALE];
        float tmax = -1e30f;
#pragma unroll
        for (int sIdx = 0; sIdx < NSCALE; sIdx++) {
            float a = lb2[sIdx];
#pragma unroll
            for (int j = 0; j < 2 * NSCALE; j++) a += t[j] * lw2[sIdx * 2 * NSCALE + j];
            tz[sIdx] = a;
            tmax = fmaxf(tmax, a);
        }
        float tsum = 0.0f;
#pragma unroll
        for (int sIdx = 0; sIdx < NSCALE; sIdx++) { tz[sIdx] = expf(tz[sIdx] - tmax); tsum += tz[sIdx]; }
        float tinv = 1.0f / tsum;
#pragma unroll
        for (int sIdx = 0; sIdx < NSCALE; sIdx++) tz[sIdx] *= tinv;

        float acc5[NSCALE];
#pragma unroll
        for (int sIdx = 0; sIdx < NSCALE; sIdx++) acc5[sIdx] = 0.0f;
#pragma unroll
        for (int r = 0; r < DH / 32; r++) {
            int idx = r * 32 + lane;
            float dg = gelu_exact(row[NH + idx]);
#pragma unroll
            for (int sIdx = 0; sIdx < NSCALE; sIdx++)
                acc5[sIdx] += dg * dw2[sIdx * DH + idx];
        }
#pragma unroll
        for (int sIdx = 0; sIdx < NSCALE; sIdx++) {
            float a = acc5[sIdx];
#pragma unroll
            for (int o = 16; o > 0; o >>= 1) a += __shfl_xor_sync(0xffffffffu, a, o);
            acc5[sIdx] = a + db2[sIdx];
        }
        float dmax = -1e30f;
#pragma unroll
        for (int sIdx = 0; sIdx < NSCALE; sIdx++) dmax = fmaxf(dmax, acc5[sIdx]);
        float dsum = 0.0f;
#pragma unroll
        for (int sIdx = 0; sIdx < NSCALE; sIdx++) { acc5[sIdx] = expf(acc5[sIdx] - dmax); dsum += acc5[sIdx]; }
        float dinv = 1.0f / dsum;
#pragma unroll
        for (int sIdx = 0; sIdx < NSCALE; sIdx++) acc5[sIdx] *= dinv;

        float w = 1.0f / (1.0f + expf(-cw[0]));
        float gg[NSCALE];
        float gs = 0.0f;
#pragma unroll
        for (int sIdx = 0; sIdx < NSCALE; sIdx++) {
            gg[sIdx] = w * tz[sIdx] + (1.0f - w) * acc5[sIdx];
            gs += gg[sIdx];
        }
        float ginv = 1.0f / gs;
        if (lane < NSCALE) {
            float v = gg[lane] * ginv;
            sg[lane] = v;
            gates_out[(size_t)b * NSCALE + lane] = v;
        }
    }
    __syncthreads();

    const float g0 = sg[0], g1 = sg[1], g2 = sg[2], g3 = sg[3], g4 = sg[4];
    const size_t rowoff = (size_t)b * DDIM;
    const size_t plane  = (size_t)BATCH * DDIM;

#pragma unroll
    for (int it = 0; it < DDIM / (256 * 4); it++) {
        int col = it * 1024 + tid * 4;
        float4 v0 = ldcs4(logits + 0 * plane + rowoff + col);
        float4 v1 = ldcs4(logits + 1 * plane + rowoff + col);
        float4 v2 = ldcs4(logits + 2 * plane + rowoff + col);
        float4 v3 = ldcs4(logits + 3 * plane + rowoff + col);
        float4 v4 = ldcs4(logits + 4 * plane + rowoff + col);
        float4 r;
        r.x = g0 * v0.x + g1 * v1.x + g2 * v2.x + g3 * v3.x + g4 * v4.x;
        r.y = g0 * v0.y + g1 * v1.y + g2 * v2.y + g3 * v3.y + g4 * v4.y;
        r.z = g0 * v0.z + g1 * v1.z + g2 * v2.z + g3 * v3.z + g4 * v4.z;
        r.w = g0 * v0.w + g1 * v1.w + g2 * v2.w + g3 * v3.w + g4 * v4.w;
        stcs4(out + rowoff + col, r);
    }
}

// ---------------------------------------------------------------------------
// Launcher. d_out layout: [combined (8192*4096 f32)] [gates (8192*5 f32)]
// ---------------------------------------------------------------------------
extern "C" void kernel_launch(void* const* d_in, const int* in_sizes, int n_in,
                              void* d_out, int out_size)
{
    const float* features = (const float*)d_in[0];
    const float* logits   = (const float*)d_in[1];
    const float* tw1      = (const float*)d_in[2];
    const float* tb1      = (const float*)d_in[3];
    const float* tg       = (const float*)d_in[4];
    const float* tbn      = (const float*)d_in[5];
    const float* tw2      = (const float*)d_in[6];
    const float* tb2      = (const float*)d_in[7];
    const float* lw1      = (const float*)d_in[8];
    const float* lb1      = (const float*)d_in[9];
    const float* lw2      = (const float*)d_in[10];
    const float* lb2      = (const float*)d_in[11];
    const float* dw1      = (const float*)d_in[12];
    const float* db1      = (const float*)d_in[13];
    const float* dw2      = (const float*)d_in[14];
    const float* db2      = (const float*)d_in[15];
    const float* cw       = (const float*)d_in[16];

    float* out = (float*)d_out;
    float* gates_out = out + (size_t)BATCH * DDIM;

    const int conv_total = A_VEC4 + W_VEC4;
    convert_kernel<<<(conv_total + 255) / 256, 256>>>(features, tw1, dw1);

    cudaFuncSetAttribute(gemm_tc_kernel,
                         cudaFuncAttributeMaxDynamicSharedMemorySize, GEMM_SMEM);
    dim3 gemm_grid(MTOT / BN, BATCH / BM);  // (11, 64)
    gemm_tc_kernel<<<gemm_grid, 256, GEMM_SMEM>>>(tb1, db1);

    combine_kernel<<<BATCH, 256>>>(logits, out, gates_out,
                                   tg, tbn, tw2, tb2, lw1, lb1, lw2, lb2,
                                   dw2, db2, cw);
}